// round 6
// baseline (speedup 1.0000x reference)
#include <cuda_runtime.h>
#include <cstdint>

// SMPL forward kinematics, HBM-bound. Round 6:
// Throughput tracks resident warps (R3/R4/R5 evidence), so: 14 persistent
// single-warp blocks per SM. NB=8 tiles (double-buffered input, single output
// staging area) -> 16,128 B smem/block; immediate per-joint STS keeps regs
// under the 146/thread needed for 14 warps.
//
// Math (G-conjugations cancel):
//   out[b,j] = out[b,P[j]] + R_{b,P[j]} * v_j,  out[b,0] = 0
//   v_j = (off[j][1], off[j][2], off[j][0])   (fixed constants, hardcoded)

#define NB    8                   // batches per tile
#define TF4   (NB * 54)           // float4 per tile, input  (432)
#define TO4   (NB * 18)           // float4 per tile, output (144)
#define BUFB  (TF4 * 16)          // bytes per input buffer (6,912)
#define BLKS_PER_SM 14
#define GRID  (152 * BLKS_PER_SM) // 2128 persistent blocks

// swizzled float4 index within a buffer for logical [e][b], b in [0,8)
#define SWZ(e, b) ((e) * NB + (((b) ^ (e)) & (NB - 1)))
// swizzled WORD index in the out area for logical word w (= 3*j + c), batch b
#define OWZ(w, b) (((((w) >> 2) * NB + ((((b) ^ ((w) >> 2)) & (NB - 1)))) << 2) + ((w) & 3))

__device__ __forceinline__ void cp_async16(uint32_t saddr, const void* gptr) {
    asm volatile("cp.async.cg.shared.global [%0], [%1], 16;\n" :: "r"(saddr), "l"(gptr));
}
__device__ __forceinline__ void cp_commit() {
    asm volatile("cp.async.commit_group;\n");
}
template<int N> __device__ __forceinline__ void cp_wait() {
    asm volatile("cp.async.wait_group %0;\n" :: "n"(N));
}

// v_j = G * off_j, from the reference's constant SMPL_OFFSETS
__device__ constexpr float VXC[24] = {0.f, 0.0372f, 0.0276f, -0.0094f, 0.0261f, -0.0383f,
    -0.0275f, 0.0121f, -0.0221f, 0.0028f, 0.0028f, -0.0014f, -0.0085f, 0.0064f, 0.0455f,
    0.078f, 0.1621f, 0.1687f, 0.055f, -0.0527f, -0.0719f, -0.1651f, -0.1708f, -0.0563f};
__device__ constexpr float VYC[24] = {0.f, -0.0522f, -0.2453f, -0.271f, -0.0383f, -0.0575f,
    -0.2436f, -0.2666f, -0.0394f, 0.079f, 0.0876f, 0.0356f, 0.1343f, 0.0565f, 0.0724f,
    0.0287f, -0.0099f, 0.0081f, -0.0068f, 0.0714f, 0.0297f, -0.0091f, 0.0043f, -0.0055f};
__device__ constexpr float VZC[24] = {0.f, -0.0112f, 0.0051f, -0.0238f, 0.0775f, -0.0086f,
    -0.0031f, -0.0219f, 0.0827f, -0.0244f, 0.017f, 0.0018f, -0.0212f, 0.032f, -0.012f,
    -0.0121f, -0.0146f, -0.0047f, -0.0099f, -0.015f, -0.0054f, -0.0198f, -0.0038f, -0.0064f};

__global__ __launch_bounds__(32, BLKS_PER_SM)
void smpl_fk_kernel(const float4* __restrict__ orient,
                    float4*       __restrict__ out,
                    int Btotal)
{
    __shared__ float4 sm[2 * TF4 + TO4];   // [2 input bufs][out area] = 16,128 B
    const int tid    = threadIdx.x;
    const int nTiles = (Btotal + NB - 1) / NB;
    int t = blockIdx.x;
    if (t >= nTiles) return;

    uint32_t smemBase;
    asm("{ .reg .u64 u; cvta.to.shared.u64 u, %1; cvt.u32.u64 %0, u; }"
        : "=r"(smemBase) : "l"(sm));

    auto prefetch = [&](int tile, int bufsel) {
        const float4*  g     = orient + (long long)tile * TF4;
        const int      total = ((Btotal - tile * NB < NB) ? (Btotal - tile * NB) : NB) * 54;
        const uint32_t sb    = smemBase + (uint32_t)bufsel * BUFB;
#pragma unroll
        for (int it = 0; it < (TF4 + 31) / 32; ++it) {   // 14 iterations
            const int idx = it * 32 + tid;
            if (idx < total) {
                const int b = idx / 54;
                const int e = idx - b * 54;
                cp_async16(sb + (uint32_t)SWZ(e, b) * 16u, g + idx);
            }
        }
        cp_commit();
    };

    prefetch(t, 0);
    int buf = 0;

    float* sow = (float*)(sm + 2 * TF4);   // out staging area (word-addressed)

    while (true) {
        const int  tn      = t + GRID;
        const bool hasNext = (tn < nTiles);
        if (hasNext) {
            prefetch(tn, buf ^ 1);
            cp_wait<1>();            // current tile complete; next still in flight
        } else {
            cp_wait<0>();
        }
        __syncthreads();

        const float4* sb = sm + buf * TF4;
        const int nb = (Btotal - t * NB < NB) ? (Btotal - t * NB) : NB;

        // ---------------- compute: lanes 0..7, one batch each; store each joint
        // ---------------- immediately to keep register liveness low ------------
        if (tid < nb) {
            float px[24], py[24], pz[24];
            constexpr int PAR[24] = {-1,0,1,2,3,0,5,6,7,0,9,10,11,12,11,14,15,16,17,11,19,20,21,22};
            px[0] = 0.f; py[0] = 0.f; pz[0] = 0.f;
            sow[OWZ(0, tid)] = 0.f;
            sow[OWZ(1, tid)] = 0.f;
            sow[OWZ(2, tid)] = 0.f;
#pragma unroll
            for (int j = 1; j < 24; ++j) {
                const int p  = PAR[j];
                const int w0 = 9 * p;      // first word of matrix p in the record
                const int c0 = w0 >> 2;    // float4 chunk (compile-time)
                const int r  = w0 & 3;     // word offset (compile-time)

                const float4 A = sb[SWZ(c0 + 0, tid)];
                const float4 Bq= sb[SWZ(c0 + 1, tid)];
                const float4 C = sb[SWZ(c0 + 2, tid)];
                float m[12];
                m[0]=A.x;  m[1]=A.y;  m[2]=A.z;  m[3]=A.w;
                m[4]=Bq.x; m[5]=Bq.y; m[6]=Bq.z; m[7]=Bq.w;
                m[8]=C.x;  m[9]=C.y;  m[10]=C.z; m[11]=C.w;

                px[j] = fmaf(m[r+0], VXC[j], fmaf(m[r+1], VYC[j], fmaf(m[r+2], VZC[j], px[p])));
                py[j] = fmaf(m[r+3], VXC[j], fmaf(m[r+4], VYC[j], fmaf(m[r+5], VZC[j], py[p])));
                pz[j] = fmaf(m[r+6], VXC[j], fmaf(m[r+7], VYC[j], fmaf(m[r+8], VZC[j], pz[p])));

                sow[OWZ(3 * j + 0, tid)] = px[j];
                sow[OWZ(3 * j + 1, tid)] = py[j];
                sow[OWZ(3 * j + 2, tid)] = pz[j];
            }
        }
        __syncthreads();   // out-area writes visible before cross-column reads

        // ---------------- write out: transposed smem -> coalesced global ----------------
        {
            float4* obase = out + (long long)t * TO4;
            const float4* so = sm + 2 * TF4;
            const int total = nb * 18;
#pragma unroll
            for (int it = 0; it < (TO4 + 31) / 32; ++it) {   // 5 iterations
                const int g = it * 32 + tid;
                if (g < total) {
                    const int b = g / 18;
                    const int e = g - b * 18;
                    obase[g] = so[SWZ(e, b)];
                }
            }
        }
        __syncthreads();   // out-area + input buffer fully consumed before reuse

        if (!hasNext) break;
        t = tn;
        buf ^= 1;
    }
}

extern "C" void kernel_launch(void* const* d_in, const int* in_sizes, int n_in,
                              void* d_out, int out_size)
{
    const float4* orient = (const float4*)d_in[0];   // (B, 24, 3, 3) fp32
    float4*       out    = (float4*)d_out;           // (B, 24, 3) fp32

    const int B = in_sizes[0] / 216;
    const int nTiles = (B + NB - 1) / NB;
    const int grid = (nTiles < GRID) ? nTiles : GRID;

    cudaFuncSetAttribute(smpl_fk_kernel,
                         cudaFuncAttributePreferredSharedMemoryCarveout, 100);
    smpl_fk_kernel<<<grid, 32>>>(orient, out, B);
}

// round 7
// speedup vs baseline: 1.6022x; 1.6022x over previous
#include <cuda_runtime.h>
#include <cstdint>

// SMPL forward kinematics, HBM-bound. Round 7:
// Loads moved off the warp LSU path onto the async bulk-copy engine
// (cp.async.bulk, UBLKCP): one instruction per 13,824 B tile, mbarrier
// completion. 8 persistent single-warp blocks/SM, double-buffered.
//
// Math (G-conjugations cancel):
//   out[b,j] = out[b,P[j]] + R_{b,P[j]} * v_j,  out[b,0] = 0
//   v_j = (off[j][1], off[j][2], off[j][0])   (fixed constants, hardcoded)

#define NB    16                  // batches per tile
#define TF4   (NB * 54)           // float4 per input tile (864)
#define TO4   (NB * 18)           // float4 per output tile (288)
#define TILEB (TF4 * 16)          // 13,824 bytes per input tile
#define OUTB  (TO4 * 16)          // 4,608 bytes per output tile
#define BLKS_PER_SM 8
#define GRID  (152 * BLKS_PER_SM) // 1216 persistent blocks

// v_j = G * off_j, from the reference's constant SMPL_OFFSETS
__device__ constexpr float VXC[24] = {0.f, 0.0372f, 0.0276f, -0.0094f, 0.0261f, -0.0383f,
    -0.0275f, 0.0121f, -0.0221f, 0.0028f, 0.0028f, -0.0014f, -0.0085f, 0.0064f, 0.0455f,
    0.078f, 0.1621f, 0.1687f, 0.055f, -0.0527f, -0.0719f, -0.1651f, -0.1708f, -0.0563f};
__device__ constexpr float VYC[24] = {0.f, -0.0522f, -0.2453f, -0.271f, -0.0383f, -0.0575f,
    -0.2436f, -0.2666f, -0.0394f, 0.079f, 0.0876f, 0.0356f, 0.1343f, 0.0565f, 0.0724f,
    0.0287f, -0.0099f, 0.0081f, -0.0068f, 0.0714f, 0.0297f, -0.0091f, 0.0043f, -0.0055f};
__device__ constexpr float VZC[24] = {0.f, -0.0112f, 0.0051f, -0.0238f, 0.0775f, -0.0086f,
    -0.0031f, -0.0219f, 0.0827f, -0.0244f, 0.017f, 0.0018f, -0.0212f, 0.032f, -0.012f,
    -0.0121f, -0.0146f, -0.0047f, -0.0099f, -0.015f, -0.0054f, -0.0198f, -0.0038f, -0.0064f};

__device__ __forceinline__ void mbar_init(uint32_t mb, uint32_t cnt) {
    asm volatile("mbarrier.init.shared::cta.b64 [%0], %1;" :: "r"(mb), "r"(cnt) : "memory");
}
__device__ __forceinline__ void bulk_load(uint32_t dst, const void* src, uint32_t bytes, uint32_t mb) {
    asm volatile("mbarrier.arrive.expect_tx.shared::cta.b64 _, [%0], %1;" :: "r"(mb), "r"(bytes) : "memory");
    asm volatile("cp.async.bulk.shared::cta.global.mbarrier::complete_tx::bytes [%0], [%1], %2, [%3];"
                 :: "r"(dst), "l"(src), "r"(bytes), "r"(mb) : "memory");
}
__device__ __forceinline__ void mbar_wait(uint32_t mb, uint32_t parity) {
    uint32_t done;
    asm volatile("{\n .reg .pred p;\n"
                 " mbarrier.try_wait.parity.acquire.cta.shared::cta.b64 p, [%1], %2;\n"
                 " selp.b32 %0, 1, 0, p;\n}"
                 : "=r"(done) : "r"(mb), "r"(parity) : "memory");
    if (!done) {
        asm volatile("{\n .reg .pred P1;\n"
                     "W%=:\n"
                     " mbarrier.try_wait.parity.acquire.cta.shared::cta.b64 P1, [%0], %1, 0x989680;\n"
                     " @P1 bra.uni D%=;\n"
                     " bra.uni W%=;\n"
                     "D%=:\n}"
                     :: "r"(mb), "r"(parity) : "memory");
    }
}

__global__ __launch_bounds__(32, BLKS_PER_SM)
void smpl_fk_kernel(const float4* __restrict__ orient,
                    float4*       __restrict__ out,
                    int Btotal)
{
    __shared__ __align__(1024) float4 buf[2 * TF4];       // two raw batch-major tiles
    __shared__ __align__(8)  unsigned long long mbars[2];
    const int tid    = threadIdx.x;
    const int nTiles = (Btotal + NB - 1) / NB;
    int t = blockIdx.x;
    if (t >= nTiles) return;

    uint32_t bufAddr, mbAddr;
    asm("{ .reg .u64 u; cvta.to.shared.u64 u, %1; cvt.u32.u64 %0, u; }" : "=r"(bufAddr) : "l"(buf));
    asm("{ .reg .u64 u; cvta.to.shared.u64 u, %1; cvt.u32.u64 %0, u; }" : "=r"(mbAddr)  : "l"(mbars));

    if (tid == 0) {
        mbar_init(mbAddr + 0, 1);
        mbar_init(mbAddr + 8, 1);
        asm volatile("fence.proxy.async.shared::cta;" ::: "memory");
    }
    __syncthreads();

    auto tile_bytes = [&](int tile) -> uint32_t {
        const int nb = (Btotal - tile * NB < NB) ? (Btotal - tile * NB) : NB;
        return (uint32_t)nb * 54u * 16u;
    };

    // prime buffer 0
    if (tid == 0)
        bulk_load(bufAddr, orient + (long long)t * TF4, tile_bytes(t), mbAddr);

    int buf_i = 0;
    int ph0 = 0, ph1 = 0;

    while (true) {
        const int  tn      = t + GRID;
        const bool hasNext = (tn < nTiles);
        if (hasNext && tid == 0)
            bulk_load(bufAddr + (uint32_t)(buf_i ^ 1) * TILEB,
                      orient + (long long)tn * TF4, tile_bytes(tn),
                      mbAddr + (uint32_t)(buf_i ^ 1) * 8u);

        // wait for current buffer
        if (buf_i == 0) { mbar_wait(mbAddr + 0, ph0); ph0 ^= 1; }
        else            { mbar_wait(mbAddr + 8, ph1); ph1 ^= 1; }
        __syncthreads();   // all threads see the filled buffer

        const float4* sb = buf + buf_i * TF4;     // batch-major records, 54 float4 each
        const int nb = (Btotal - t * NB < NB) ? (Btotal - t * NB) : NB;

        // ---------------- compute: lanes 0..15, one batch each (AoS smem reads) ----
        float px[24], py[24], pz[24];
        if (tid < nb) {
            const float4* rec = sb + tid * 54;
            constexpr int PAR[24] = {-1,0,1,2,3,0,5,6,7,0,9,10,11,12,11,14,15,16,17,11,19,20,21,22};
            px[0] = 0.f; py[0] = 0.f; pz[0] = 0.f;
#pragma unroll
            for (int j = 1; j < 24; ++j) {
                const int p  = PAR[j];
                const int w0 = 9 * p;      // first word of matrix p in the record
                const int c0 = w0 >> 2;    // float4 chunk (compile-time)
                const int r  = w0 & 3;     // word offset (compile-time)

                const float4 A = rec[c0 + 0];
                const float4 Bq= rec[c0 + 1];
                const float4 C = rec[c0 + 2];
                float m[12];
                m[0]=A.x;  m[1]=A.y;  m[2]=A.z;  m[3]=A.w;
                m[4]=Bq.x; m[5]=Bq.y; m[6]=Bq.z; m[7]=Bq.w;
                m[8]=C.x;  m[9]=C.y;  m[10]=C.z; m[11]=C.w;

                px[j] = fmaf(m[r+0], VXC[j], fmaf(m[r+1], VYC[j], fmaf(m[r+2], VZC[j], px[p])));
                py[j] = fmaf(m[r+3], VXC[j], fmaf(m[r+4], VYC[j], fmaf(m[r+5], VZC[j], py[p])));
                pz[j] = fmaf(m[r+6], VXC[j], fmaf(m[r+7], VYC[j], fmaf(m[r+8], VZC[j], pz[p])));
            }
        }
        __syncthreads();   // all record reads done before staging overwrites the buffer

        // ---------------- stage out: batch-major output into head of consumed buffer
        float* sow = (float*)(buf + buf_i * TF4);
        if (tid < nb) {
            float* dst = sow + tid * 72;           // 24 joints * 3 words, contiguous
#pragma unroll
            for (int j = 0; j < 24; ++j) {
                dst[3 * j + 0] = px[j];
                dst[3 * j + 1] = py[j];
                dst[3 * j + 2] = pz[j];
            }
        }
        __syncthreads();

        // ---------------- write out: straight coalesced smem -> gmem copy ----------
        {
            const float4* so = buf + buf_i * TF4;
            float4* obase = out + (long long)t * TO4;
            const int total = nb * 18;
#pragma unroll
            for (int it = 0; it < (TO4 + 31) / 32; ++it) {   // 9 iterations
                const int g = it * 32 + tid;
                if (g < total) obase[g] = so[g];
            }
        }
        __syncthreads();   // buffer fully consumed before it is a bulk-load target again

        if (!hasNext) break;
        t = tn;
        buf_i ^= 1;
    }
}

extern "C" void kernel_launch(void* const* d_in, const int* in_sizes, int n_in,
                              void* d_out, int out_size)
{
    const float4* orient = (const float4*)d_in[0];   // (B, 24, 3, 3) fp32
    float4*       out    = (float4*)d_out;           // (B, 24, 3) fp32

    const int B = in_sizes[0] / 216;
    const int nTiles = (B + NB - 1) / NB;
    const int grid = (nTiles < GRID) ? nTiles : GRID;

    cudaFuncSetAttribute(smpl_fk_kernel,
                         cudaFuncAttributePreferredSharedMemoryCarveout, 100);
    smpl_fk_kernel<<<grid, 32>>>(orient, out, B);
}